// round 3
// baseline (speedup 1.0000x reference)
#include <cuda_runtime.h>
#include <math.h>

typedef unsigned long long ull;

#define NBC   6   // B*C
#define NLEV  6
#define NSTAT 9   // S1 S2 S3 S4 S5 Sm1 Sm2 T2(log2) count

// Global accumulators + pyramid scratch (static __device__ arrays: allocation-free)
__device__ double g_acc[NBC][NLEV][NSTAT];
__device__ float  g_l1[6 * 64 * 64 * 64];
__device__ float  g_l2[6 * 32 * 32 * 32];
__device__ float  g_l3[6 * 16 * 16 * 16];
__device__ float  g_l4[6 * 8 * 8 * 8];
__device__ float  g_l5[6 * 4 * 4 * 4];
__device__ float  g_l6[6 * 2 * 2 * 2];

// ---- packed f32x2 helpers (Blackwell 2xFP32 path; ptxas won't auto-emit) ----
__device__ __forceinline__ ull pk2(float lo, float hi) {
    ull r; asm("mov.b64 %0, {%1, %2};" : "=l"(r) : "f"(lo), "f"(hi)); return r;
}
__device__ __forceinline__ float2 upk2(ull v) {
    float2 f; asm("mov.b64 {%0, %1}, %2;" : "=f"(f.x), "=f"(f.y) : "l"(v)); return f;
}
__device__ __forceinline__ ull add2(ull a, ull b) {
    ull r; asm("add.rn.f32x2 %0, %1, %2;" : "=l"(r) : "l"(a), "l"(b)); return r;
}
__device__ __forceinline__ ull mul2(ull a, ull b) {
    ull r; asm("mul.rn.f32x2 %0, %1, %2;" : "=l"(r) : "l"(a), "l"(b)); return r;
}
__device__ __forceinline__ ull fma2(ull a, ull b, ull c) {
    ull r; asm("fma.rn.f32x2 %0, %1, %2, %3;" : "=l"(r) : "l"(a), "l"(b), "l"(c)); return r;
}
__device__ __forceinline__ float rcpa(float x) {
    float r; asm("rcp.approx.f32 %0, %1;" : "=f"(r) : "f"(x)); return r;
}
__device__ __forceinline__ float lg2a(float x) {
    float r; asm("lg2.approx.f32 %0, %1;" : "=f"(r) : "f"(x)); return r;
}

__global__ void zero_acc_kernel() {
    int t = threadIdx.x;
    if (t < NBC * NLEV * NSTAT) ((double*)g_acc)[t] = 0.0;
}

// Fused: compute moment stats of level `LEVEL` input and write 2x2x2 sum-pooled
// next level. IB = log2(input spatial dim). grid = (blocks_per_bc, 6).
template <int IB>
__global__ void __launch_bounds__(256) stats_pool_kernel(const float* __restrict__ img) {
    constexpr int OB   = IB - 1;
    constexpr int IN   = 1 << IB;
    constexpr int OUT3 = 1 << (3 * OB);

    const float* in; float* out; int level;
    if constexpr (IB == 7)      { in = img;  out = g_l2 ? g_l1 : g_l1; level = 0; }
    else if constexpr (IB == 6) { in = g_l1; out = g_l2; level = 1; }
    else if constexpr (IB == 5) { in = g_l2; out = g_l3; level = 2; }
    else if constexpr (IB == 4) { in = g_l3; out = g_l4; level = 3; }
    else if constexpr (IB == 3) { in = g_l4; out = g_l5; level = 4; }
    else                        { in = g_l5; out = g_l6; level = 5; }

    const int bc = blockIdx.y;
    const float* inp  = in  + ((size_t)bc << (3 * IB));
    float*       outp = out + ((size_t)bc << (3 * OB));

    ull S1 = 0, S2 = 0, S3 = 0, S4 = 0, S5 = 0, Sm1 = 0, Sm2 = 0, T2 = 0;
    unsigned int cnt = 0;

    const int stride = gridDim.x * blockDim.x;
    for (int idx = blockIdx.x * blockDim.x + threadIdx.x; idx < OUT3; idx += stride) {
        int ow = idx & ((1 << OB) - 1);
        int oh = (idx >> OB) & ((1 << OB) - 1);
        int od = idx >> (2 * OB);
        int base = (od << (2 * IB + 1)) + (oh << (IB + 1)) + (ow << 1);

        float2 v0 = *reinterpret_cast<const float2*>(inp + base);
        float2 v1 = *reinterpret_cast<const float2*>(inp + base + IN);
        float2 v2 = *reinterpret_cast<const float2*>(inp + base + IN * IN);
        float2 v3 = *reinterpret_cast<const float2*>(inp + base + IN * IN + IN);

        float mn = fminf(fminf(fminf(v0.x, v0.y), fminf(v1.x, v1.y)),
                         fminf(fminf(v2.x, v2.y), fminf(v3.x, v3.y)));
        float psum;
        if (mn != 0.0f) {
            // fast path: all 8 voxels nonzero
            ull xs[4];
            xs[0] = pk2(v0.x, v0.y); xs[1] = pk2(v1.x, v1.y);
            xs[2] = pk2(v2.x, v2.y); xs[3] = pk2(v3.x, v3.y);
            ull pacc = add2(add2(xs[0], xs[1]), add2(xs[2], xs[3]));
#pragma unroll
            for (int j = 0; j < 4; j++) {
                ull x = xs[j];
                float2 f = upk2(x);
                ull inv = pk2(rcpa(f.x), rcpa(f.y));   // MUFU.RCP x2
                ull lg  = pk2(lg2a(f.x), lg2a(f.y));   // MUFU.LG2 x2
                S1 = add2(S1, x);
                ull xx = mul2(x, x);
                S2 = add2(S2, xx);
                ull xxx = mul2(xx, x);
                S3 = add2(S3, xxx);
                S4 = fma2(xx, xx, S4);
                S5 = fma2(xxx, xx, S5);
                Sm1 = add2(Sm1, inv);
                Sm2 = fma2(inv, inv, Sm2);
                T2 = fma2(x, lg, T2);
            }
            cnt += 8;
            float2 pv = upk2(pacc);
            psum = pv.x + pv.y;
        } else {
            // rare slow path (exact zeros): direct double atomics, skip zeros
            float vals[8] = {v0.x, v0.y, v1.x, v1.y, v2.x, v2.y, v3.x, v3.y};
            psum = 0.0f;
            double* acc = g_acc[bc][level];
            for (int j = 0; j < 8; j++) {
                float v = vals[j];
                psum += v;
                if (v != 0.0f) {
                    double dv = (double)v;
                    double d2 = dv * dv;
                    atomicAdd(&acc[0], dv);
                    atomicAdd(&acc[1], d2);
                    atomicAdd(&acc[2], d2 * dv);
                    atomicAdd(&acc[3], d2 * d2);
                    atomicAdd(&acc[4], d2 * d2 * dv);
                    atomicAdd(&acc[5], 1.0 / dv);
                    atomicAdd(&acc[6], 1.0 / d2);
                    atomicAdd(&acc[7], dv * log2(dv));
                    atomicAdd(&acc[8], 1.0);
                }
            }
        }
        outp[idx] = psum;
    }

    // ---- block reduction (doubles) + atomicAdd into g_acc ----
    double vals[9];
    {
        float2 f;
        f = upk2(S1);  vals[0] = (double)f.x + (double)f.y;
        f = upk2(S2);  vals[1] = (double)f.x + (double)f.y;
        f = upk2(S3);  vals[2] = (double)f.x + (double)f.y;
        f = upk2(S4);  vals[3] = (double)f.x + (double)f.y;
        f = upk2(S5);  vals[4] = (double)f.x + (double)f.y;
        f = upk2(Sm1); vals[5] = (double)f.x + (double)f.y;
        f = upk2(Sm2); vals[6] = (double)f.x + (double)f.y;
        f = upk2(T2);  vals[7] = (double)f.x + (double)f.y;
        vals[8] = (double)cnt;
    }
#pragma unroll
    for (int j = 0; j < 9; j++)
#pragma unroll
        for (int off = 16; off; off >>= 1)
            vals[j] += __shfl_down_sync(0xFFFFFFFFu, vals[j], off);

    __shared__ double sm[8][9];
    int lane = threadIdx.x & 31, warp = threadIdx.x >> 5;
    if (lane == 0)
        for (int j = 0; j < 9; j++) sm[warp][j] = vals[j];
    __syncthreads();
    int nw = blockDim.x >> 5;
    if (threadIdx.x < 9) {
        double s = 0.0;
        for (int w = 0; w < nw; w++) s += sm[w][threadIdx.x];
        atomicAdd(&g_acc[bc][level][threadIdx.x], s);
    }
}

// Final slope: one block, 48 threads, double precision.
__global__ void finalize_kernel(const int* __restrict__ bounds, float* __restrict__ out) {
    int t = threadIdx.x;
    if (t >= NBC * 8) return;
    int bc = t >> 3;
    int k  = bounds[t & 7];

    double b   = g_acc[bc][0][0];  // total sum (level-0 S1)
    double lnb = log(b);

    double sp = 0.0, spq = 0.0;
    for (int s = 0; s < NLEV; s++) {
        const double* a = g_acc[bc][s];
        double p;
        if (k == 1) {
            p = (a[7] * M_LN2) / b - lnb;           // sum x*ln(x)/b - ln b
        } else if (k == 0) {
            p = log(a[8]);                           // log(nonzero count)
        } else {
            double S;
            switch (k) {
                case  2: S = a[1]; break;
                case  3: S = a[2]; break;
                case  4: S = a[3]; break;
                case  5: S = a[4]; break;
                case -1: S = a[5]; break;
                case -2: S = a[6]; break;
                default: S = nan(""); break;
            }
            p = log(S) - (double)k * lnb;            // log(sum (x/b)^k)
        }
        sp  += p;
        spq += p * ((double)s * M_LN2);
    }
    const double qs  = 15.0 * M_LN2;
    const double q2s = 55.0 * M_LN2 * M_LN2;
    const double den = 6.0 * q2s - qs * qs;
    double aa = (k == 1) ? 1.0 : 1.0 / (double)(k - 1);
    out[t] = (float)(aa * (6.0 * spq - sp * qs) / den);
}

extern "C" void kernel_launch(void* const* d_in, const int* in_sizes, int n_in,
                              void* d_out, int out_size) {
    const float* img    = (const float*)d_in[0];
    const int*   bounds = (const int*)d_in[1];
    float*       out    = (float*)d_out;

    zero_acc_kernel<<<1, 512>>>();
    stats_pool_kernel<7><<<dim3(192, 6), 256>>>(img);      // 128^3 -> stats L0 + write 64^3
    stats_pool_kernel<6><<<dim3(32, 6), 256>>>(nullptr);   // 64^3  -> stats L1 + write 32^3
    stats_pool_kernel<5><<<dim3(8, 6), 256>>>(nullptr);    // 32^3  -> stats L2 + write 16^3
    stats_pool_kernel<4><<<dim3(2, 6), 256>>>(nullptr);    // 16^3  -> stats L3 + write 8^3
    stats_pool_kernel<3><<<dim3(1, 6), 64>>>(nullptr);     // 8^3   -> stats L4 + write 4^3
    stats_pool_kernel<2><<<dim3(1, 6), 32>>>(nullptr);     // 4^3   -> stats L5 + write 2^3 (unused)
    finalize_kernel<<<1, 64>>>(bounds, out);
}